// round 14
// baseline (speedup 1.0000x reference)
#include <cuda_runtime.h>
#include <math.h>

// One CTA per batch. 64 threads. Matrix in smem with stride-65 padding
// (conflict-free for both row and column access by 64 threads).
//
// Phase 1: x = exp(logits/(temp+1e-6) - global_max)
// Phase 2: 30 sinkhorn iterations (row normalize then col normalize),
//          elementwise exactly like the reference: x = x / (sum + 1e-8)
//          implemented as one precise reciprocal per row/col + multiply.
// Phase 3: greedy unique argmax == iterated masked global argmax with
//          tie-break on smallest flat index (encoded in a monotone u64 key).
//          Maintained per-row maxima; a row rescans only when the removed
//          column was its cached argmax.
// Phase 4: write hard permutation (output == w_hard exactly).

#define STRIDE 65
#define NITER 30

__global__ __launch_bounds__(64)
void sinkhorn_greedy_kernel(const float* __restrict__ cell_logits,
                            const float* __restrict__ pos_temp,
                            float* __restrict__ out)
{
    __shared__ float sm[64 * STRIDE];
    __shared__ unsigned long long red[2];
    __shared__ int asn[64];

    const int b    = blockIdx.x;
    const int t    = threadIdx.x;      // 0..63
    const int warp = t >> 5;
    const int lane = t & 31;

    const float it = pos_temp[0] + 1e-6f;
    const float* __restrict__ g = cell_logits + (size_t)b * 4096;

    // ---- cooperative coalesced load, scaled by 1/(temp+1e-6) ----
#pragma unroll
    for (int j = 0; j < 64; j++) {
        sm[j * STRIDE + t] = g[j * 64 + t] / it;   // 256B coalesced per step
    }
    __syncthreads();

    // ---- global max over the 64x64 matrix ----
    float v[64];
    float mx = -INFINITY;
#pragma unroll
    for (int c = 0; c < 64; c++) {
        v[c] = sm[t * STRIDE + c];
        mx = fmaxf(mx, v[c]);
    }
#pragma unroll
    for (int o = 16; o; o >>= 1)
        mx = fmaxf(mx, __shfl_xor_sync(0xffffffffu, mx, o));
    if (lane == 0) red[warp] = (unsigned long long)__float_as_uint(mx);
    __syncthreads();
    const float gmax = fmaxf(__uint_as_float((unsigned)red[0]),
                             __uint_as_float((unsigned)red[1]));

    // ---- x = exp(scaled - gmax) ----
#pragma unroll
    for (int c = 0; c < 64; c++)
        sm[t * STRIDE + c] = expf(v[c] - gmax);
    __syncthreads();

    // ---- 30 sinkhorn iterations ----
    for (int iter = 0; iter < NITER; iter++) {
        // row normalize: thread t owns row t
        float s = 0.0f;
#pragma unroll
        for (int c = 0; c < 64; c++) {
            v[c] = sm[t * STRIDE + c];
            s += v[c];
        }
        float inv = 1.0f / (s + 1e-8f);
#pragma unroll
        for (int c = 0; c < 64; c++)
            sm[t * STRIDE + c] = v[c] * inv;
        __syncthreads();

        // col normalize: thread t owns column t
        s = 0.0f;
#pragma unroll
        for (int k = 0; k < 64; k++) {
            v[k] = sm[k * STRIDE + t];
            s += v[k];
        }
        inv = 1.0f / (s + 1e-8f);
#pragma unroll
        for (int k = 0; k < 64; k++)
            sm[k * STRIDE + t] = v[k] * inv;
        __syncthreads();
    }

    // ---- greedy unique argmax ----
    // Load my row into registers (all entries strictly > 0).
#pragma unroll
    for (int c = 0; c < 64; c++)
        v[c] = sm[t * STRIDE + c];

    unsigned cm0 = 0u, cm1 = 0u;   // used-column bitmask (replicated per thread)
    bool rowfree = true;

    // initial per-row max (no columns used yet)
    float best = -1.0f;
    int   bc   = 0;
#pragma unroll
    for (int c = 0; c < 64; c++) {
        if (v[c] > best) { best = v[c]; bc = c; }
    }

    for (int it2 = 0; it2 < 64; it2++) {
        // monotone key: larger value wins; tie -> smaller flat index (r*64+c)
        unsigned long long key = 0ull;
        if (rowfree) {
            unsigned flat = (unsigned)(t * 64 + bc);
            key = ((unsigned long long)__float_as_uint(best) << 32)
                | (unsigned long long)(4095u - flat);
        }
#pragma unroll
        for (int o = 16; o; o >>= 1) {
            unsigned long long ok = __shfl_xor_sync(0xffffffffu, key, o);
            if (ok > key) key = ok;
        }
        if (lane == 0) red[warp] = key;
        __syncthreads();

        unsigned long long k0 = red[0], k1 = red[1];
        unsigned long long kw = (k0 > k1) ? k0 : k1;
        unsigned flat = 4095u - (unsigned)(kw & 0xffffffffull);
        int wr = (int)(flat >> 6);
        int wc = (int)(flat & 63u);

        if (t == wr) { rowfree = false; asn[wr] = wc; }
        if (wc < 32) cm0 |= (1u << wc);
        else         cm1 |= (1u << (wc - 32));

        // rescan only if my cached argmax column just got consumed
        bool resc = rowfree && (bc == wc);
        if (resc) {
            best = -1.0f; bc = 0;
#pragma unroll
            for (int c = 0; c < 64; c++) {
                bool used = (c < 32) ? (((cm0 >> c) & 1u) != 0u)
                                     : (((cm1 >> (c - 32)) & 1u) != 0u);
                if (!used && v[c] > best) { best = v[c]; bc = c; }
            }
        }
        __syncthreads();   // protect red[] before next iteration's write
    }

    // ---- write hard permutation, coalesced ----
    float* __restrict__ o = out + (size_t)b * 4096;
#pragma unroll
    for (int j = 0; j < 64; j++) {
        o[j * 64 + t] = (t == asn[j]) ? 1.0f : 0.0f;
    }
}

extern "C" void kernel_launch(void* const* d_in, const int* in_sizes, int n_in,
                              void* d_out, int out_size)
{
    const float* cell_logits = (const float*)d_in[0];
    const float* pos_temp    = (const float*)d_in[1];
    float* out               = (float*)d_out;

    const int B = in_sizes[0] / 4096;   // 4096 batches of 64x64
    sinkhorn_greedy_kernel<<<B, 64>>>(cell_logits, pos_temp, out);
}

// round 15
// speedup vs baseline: 1.2699x; 1.2699x over previous
#include <cuda_runtime.h>
#include <math.h>

// One CTA per batch (B=4096), 64 threads, thread t = row t (and column t in
// the column phase).
//
// Factored sinkhorn: the iterate is always x = diag(u) * E * diag(v) with
// E = exp(a/(temp+1e-6) - gmax) FIXED.
//   row phase: S_r = sum_c E[r][c]*v[c];  u_r *= 1/(u_r*S_r + 1e-8)
//   col phase: S_c = sum_r u[r]*E[r][c];  v_c *= 1/(v_c*S_c + 1e-8)
// E row lives in registers; E^T lives in smem (written once, read-only) with
// stride-68 padding so column reads are contiguous, 16B-aligned, conflict-free
// LDS.128. u/v scale vectors are broadcast LDS.128.
//
// Greedy unique argmax: iterated masked global argmax with tie-break on
// smallest flat index via a monotone u64 key; maintained per-row maxima with
// rescan only when the consumed column was the cached argmax. One barrier per
// pick (double-buffered reduction slots).

#define ST 68          // E^T row stride in words: 16B-aligned rows, f4-conflict-free
#define NITER 30

__global__ __launch_bounds__(64)
void sinkhorn_greedy_kernel(const float* __restrict__ cell_logits,
                            const float* __restrict__ pos_temp,
                            float* __restrict__ out)
{
    __shared__ float smT[64 * ST];                    // E^T: smT[c*ST + r]
    __shared__ __align__(16) float us[64];
    __shared__ __align__(16) float vs[64];
    __shared__ unsigned long long red[2][2];
    __shared__ int asn[64];

    const int b    = blockIdx.x;
    const int t    = threadIdx.x;        // 0..63
    const int warp = t >> 5;
    const int lane = t & 31;

    const float it = pos_temp[0] + 1e-6f;
    const float sc = 1.0f / it;

    // ---- load my row (LDG.128), scale, row max ----
    const float4* __restrict__ g4 =
        (const float4*)(cell_logits + (size_t)b * 4096 + (size_t)t * 64);

    float ex[64];
    float mx = -INFINITY;
#pragma unroll
    for (int k = 0; k < 16; k++) {
        float4 a = g4[k];
        ex[4*k+0] = a.x * sc;  ex[4*k+1] = a.y * sc;
        ex[4*k+2] = a.z * sc;  ex[4*k+3] = a.w * sc;
        mx = fmaxf(mx, fmaxf(fmaxf(ex[4*k+0], ex[4*k+1]),
                             fmaxf(ex[4*k+2], ex[4*k+3])));
    }
#pragma unroll
    for (int o = 16; o; o >>= 1)
        mx = fmaxf(mx, __shfl_xor_sync(0xffffffffu, mx, o));
    if (lane == 0) red[0][warp] = (unsigned long long)__float_as_uint(mx);
    __syncthreads();
    const float gmax = fmaxf(__uint_as_float((unsigned)red[0][0]),
                             __uint_as_float((unsigned)red[0][1]));

    // ---- E = exp(scaled - gmax); write E^T to smem; init scales ----
#pragma unroll
    for (int c = 0; c < 64; c++) {
        ex[c] = expf(ex[c] - gmax);
        smT[c * ST + t] = ex[c];          // conflict-free scalar STS
    }
    us[t] = 1.0f;
    vs[t] = 1.0f;
    __syncthreads();

    float u = 1.0f, vcol = 1.0f;
    const float4* __restrict__ vs4 = (const float4*)vs;
    const float4* __restrict__ us4 = (const float4*)us;
    const float4* __restrict__ myT = (const float4*)(smT + (size_t)t * ST);

    // ---- 30 sinkhorn iterations on the scale vectors only ----
    for (int iter = 0; iter < NITER; iter++) {
        // row phase (thread t = row t): E row in regs, v broadcast from smem
        float s = 0.0f;
#pragma unroll
        for (int k = 0; k < 16; k++) {
            float4 vv = vs4[k];
            s += ex[4*k+0]*vv.x + ex[4*k+1]*vv.y
               + ex[4*k+2]*vv.z + ex[4*k+3]*vv.w;
        }
        u *= 1.0f / (u * s + 1e-8f);
        us[t] = u;
        __syncthreads();

        // col phase (thread t = col t): E^T row contiguous, u broadcast
        s = 0.0f;
#pragma unroll
        for (int k = 0; k < 16; k++) {
            float4 ee = myT[k];
            float4 uu = us4[k];
            s += ee.x*uu.x + ee.y*uu.y + ee.z*uu.z + ee.w*uu.w;
        }
        vcol *= 1.0f / (vcol * s + 1e-8f);
        vs[t] = vcol;
        __syncthreads();
    }

    // ---- materialize my row of x = u * E * diag(v) into registers ----
#pragma unroll
    for (int k = 0; k < 16; k++) {
        float4 vv = vs4[k];
        ex[4*k+0] = u * ex[4*k+0] * vv.x;
        ex[4*k+1] = u * ex[4*k+1] * vv.y;
        ex[4*k+2] = u * ex[4*k+2] * vv.z;
        ex[4*k+3] = u * ex[4*k+3] * vv.w;
    }

    // ---- greedy unique argmax (one barrier per pick) ----
    unsigned cm0 = 0u, cm1 = 0u;
    bool rowfree = true;
    float best = -1.0f;
    int   bc   = 0;
#pragma unroll
    for (int c = 0; c < 64; c++)
        if (ex[c] > best) { best = ex[c]; bc = c; }

    for (int it2 = 0; it2 < 64; it2++) {
        const int par = it2 & 1;
        unsigned long long key = 0ull;
        if (rowfree) {
            unsigned flat = (unsigned)(t * 64 + bc);
            key = ((unsigned long long)__float_as_uint(best) << 32)
                | (unsigned long long)(4095u - flat);
        }
#pragma unroll
        for (int o = 16; o; o >>= 1) {
            unsigned long long ok = __shfl_xor_sync(0xffffffffu, key, o);
            if (ok > key) key = ok;
        }
        if (lane == 0) red[par][warp] = key;
        __syncthreads();

        unsigned long long k0 = red[par][0], k1 = red[par][1];
        unsigned long long kw = (k0 > k1) ? k0 : k1;
        unsigned flat = 4095u - (unsigned)(kw & 0xffffffffull);
        int wr = (int)(flat >> 6);
        int wc = (int)(flat & 63u);

        if (t == wr) { rowfree = false; asn[wr] = wc; }
        if (wc < 32) cm0 |= (1u << wc);
        else         cm1 |= (1u << (wc - 32));

        if (rowfree && bc == wc) {      // cached argmax consumed -> rescan
            best = -1.0f; bc = 0;
#pragma unroll
            for (int c = 0; c < 64; c++) {
                bool used = (c < 32) ? (((cm0 >> c) & 1u) != 0u)
                                     : (((cm1 >> (c - 32)) & 1u) != 0u);
                if (!used && ex[c] > best) { best = ex[c]; bc = c; }
            }
        }
        // no trailing barrier: next pick writes the other red[] buffer
    }
    __syncthreads();                     // asn[] complete

    // ---- write hard permutation: my row, 16 x STG.128 ----
    const int a = asn[t];
    float4* __restrict__ o4 = (float4*)(out + (size_t)b * 4096 + (size_t)t * 64);
#pragma unroll
    for (int k = 0; k < 16; k++) {
        float4 z;
        z.x = (a == 4*k+0) ? 1.0f : 0.0f;
        z.y = (a == 4*k+1) ? 1.0f : 0.0f;
        z.z = (a == 4*k+2) ? 1.0f : 0.0f;
        z.w = (a == 4*k+3) ? 1.0f : 0.0f;
        o4[k] = z;
    }
}

extern "C" void kernel_launch(void* const* d_in, const int* in_sizes, int n_in,
                              void* d_out, int out_size)
{
    const float* cell_logits = (const float*)d_in[0];
    const float* pos_temp    = (const float*)d_in[1];
    float* out               = (float*)d_out;

    const int B = in_sizes[0] / 4096;   // 4096 batches of 64x64
    sinkhorn_greedy_kernel<<<B, 64>>>(cell_logits, pos_temp, out);
}